// round 1
// baseline (speedup 1.0000x reference)
#include <cuda_runtime.h>
#include <math.h>

#define NN   50000
#define NB   4096
#define NEX  8
#define EMBD 64

// 16B-aligned device scratch (no allocations allowed)
__device__ __align__(16) float g_xw[NN * 64];
__device__ __align__(16) float g_agg[NN * 64];
__device__ __align__(16) float g_h[NN * 64];
__device__ __align__(16) float g_dinv[NN];
__device__ __align__(16) float g_pool[NB * 64];
__device__ __align__(16) float g_cnt[2 * NB];
__device__ float g_loss[1];

static __device__ __forceinline__ void red_add_v4(float4* p, float4 v) {
    asm volatile("red.global.add.v4.f32 [%0], {%1, %2, %3, %4};"
                 :: "l"(p), "f"(v.x), "f"(v.y), "f"(v.z), "f"(v.w)
                 : "memory");
}

// ---------------- degree / dinv ----------------
__global__ void k_deg(const int* __restrict__ dst, int E) {
    int e = blockIdx.x * blockDim.x + threadIdx.x;
    if (e < E) atomicAdd(&g_dinv[dst[e]], 1.0f);
}

__global__ void k_dinv(int n) {
    int i = blockIdx.x * blockDim.x + threadIdx.x;
    if (i < n) g_dinv[i] = rsqrtf(g_dinv[i] + 1.0f);
}

// ---------------- GEMM: Y(g_xw) = X @ W, X is [n,64], W is [64,KOUT] ----------------
template <int KOUT>
__global__ void k_gemm(const float* __restrict__ X, const float* __restrict__ W, int n) {
    __shared__ float Ws[64 * KOUT];
    for (int i = threadIdx.x; i < 64 * KOUT; i += blockDim.x) Ws[i] = W[i];
    __syncthreads();
    int row = blockIdx.x * blockDim.x + threadIdx.x;
    if (row >= n) return;

    float xr[64];
    const float4* x4 = (const float4*)(X + row * 64);
#pragma unroll
    for (int j = 0; j < 16; j++) {
        float4 v = x4[j];
        xr[4 * j + 0] = v.x; xr[4 * j + 1] = v.y;
        xr[4 * j + 2] = v.z; xr[4 * j + 3] = v.w;
    }
    float acc[KOUT];
#pragma unroll
    for (int c = 0; c < KOUT; c++) acc[c] = 0.0f;
    for (int k = 0; k < 64; k++) {
        float xk = xr[k];
#pragma unroll
        for (int c = 0; c < KOUT; c++) acc[c] += xk * Ws[k * KOUT + c];
    }
    float4* y4 = (float4*)(g_xw + row * KOUT);
#pragma unroll
    for (int j = 0; j < KOUT / 4; j++)
        y4[j] = make_float4(acc[4 * j], acc[4 * j + 1], acc[4 * j + 2], acc[4 * j + 3]);
}

// ---------------- edge scatter: agg[dst] += xw[src] * dinv[src]*dinv[dst] ----------------
template <int C4>  // C4 = channels/4 (16 for C=64, 8 for C=32)
__global__ void k_scatter(const int* __restrict__ src, const int* __restrict__ dst, int E) {
    int idx = blockIdx.x * blockDim.x + threadIdx.x;
    int e = idx / C4;
    int q = idx - e * C4;
    if (e >= E) return;
    int s = src[e], d = dst[e];
    float nrm = g_dinv[s] * g_dinv[d];
    float4 v = ((const float4*)g_xw)[s * C4 + q];
    float4 m = make_float4(v.x * nrm, v.y * nrm, v.z * nrm, v.w * nrm);
    red_add_v4(((float4*)g_agg) + d * C4 + q, m);
}

// ---------------- h = agg + dinv^2 * xw + bias ----------------
template <int C4>
__global__ void k_selfbias(const float* __restrict__ bias, int n) {
    int idx = blockIdx.x * blockDim.x + threadIdx.x;
    if (idx >= n * C4) return;
    int i = idx / C4;
    int q = idx - i * C4;
    float di = g_dinv[i];
    float sl = di * di;
    float4 a = ((const float4*)g_agg)[idx];
    float4 x = ((const float4*)g_xw)[idx];
    float4 b = ((const float4*)bias)[q];
    ((float4*)g_h)[idx] = make_float4(a.x + sl * x.x + b.x,
                                      a.y + sl * x.y + b.y,
                                      a.z + sl * x.z + b.z,
                                      a.w + sl * x.w + b.w);
}

// ---------------- mean-pool accumulate (h2 is [n,32]) ----------------
__global__ void k_pool(const int* __restrict__ batch, int n, int scale) {
    int idx = blockIdx.x * blockDim.x + threadIdx.x;
    if (idx >= n * 8) return;
    int i = idx >> 3;
    int q = idx & 7;
    int b = batch[i];
    float4 v = ((const float4*)g_h)[i * 8 + q];
    red_add_v4((float4*)(g_pool + b * 64 + scale * 32) + q, v);
    if (q == 0) atomicAdd(&g_cnt[scale * NB + b], 1.0f);
}

// ---------------- gate = softmax(concat(x0,x1) @ Wc + bc) ----------------
__global__ void k_gate(const float* __restrict__ Wc, const float* __restrict__ bc,
                       float* __restrict__ out, int B) {
    int b = blockIdx.x * blockDim.x + threadIdx.x;
    if (b >= B) return;
    float inv0 = 1.0f / fmaxf(g_cnt[b], 1.0f);
    float inv1 = 1.0f / fmaxf(g_cnt[NB + b], 1.0f);
    float logit[NEX];
#pragma unroll
    for (int e = 0; e < NEX; e++) logit[e] = bc[e];
    const float* pr = g_pool + b * 64;
    for (int k = 0; k < 64; k++) {
        float xv = pr[k] * (k < 32 ? inv0 : inv1);
#pragma unroll
        for (int e = 0; e < NEX; e++) logit[e] += xv * Wc[k * NEX + e];
    }
    float m = logit[0];
#pragma unroll
    for (int e = 1; e < NEX; e++) m = fmaxf(m, logit[e]);
    float ssum = 0.0f;
#pragma unroll
    for (int e = 0; e < NEX; e++) { logit[e] = expf(logit[e] - m); ssum += logit[e]; }
    float is = 1.0f / ssum;
#pragma unroll
    for (int e = 0; e < NEX; e++) out[b * NEX + e] = logit[e] * is;
}

// ---------------- distortion loss: one warp per graph edge ----------------
__global__ void k_loss(const float* __restrict__ emb, const float* __restrict__ gate,
                       const float* __restrict__ dis, const int* __restrict__ ei2, int E2) {
    int gidx = blockIdx.x * blockDim.x + threadIdx.x;
    int e = gidx >> 5;
    int lane = threadIdx.x & 31;
    if (e >= E2) return;
    int s = ei2[e];
    int d = ei2[E2 + e];
    int ex = lane >> 2;   // expert slice this lane covers
    int ch = lane & 3;
    const float4* A = (const float4*)(emb + (long)s * (NEX * EMBD)) + ex * 16 + ch * 4;
    const float4* Bp = (const float4*)(emb + (long)d * (NEX * EMBD)) + ex * 16 + ch * 4;
    float acc = 0.0f;
#pragma unroll
    for (int j = 0; j < 4; j++) {
        float4 a = A[j], b = Bp[j];
        float dx = a.x - b.x, dy = a.y - b.y, dz = a.z - b.z, dw = a.w - b.w;
        acc += dx * dx + dy * dy + dz * dz + dw * dw;
    }
    // reduce within each 4-lane group -> per-expert squared distance
    acc += __shfl_xor_sync(0xffffffffu, acc, 1);
    acc += __shfl_xor_sync(0xffffffffu, acc, 2);
    // lane l (within 8-lane segment) picks up expert (l&7)'s value from lane (l&7)*4
    float de = __shfl_sync(0xffffffffu, acc, (lane & 7) * 4);
    int myex = lane & 7;
    float gp = gate[s * NEX + myex] * gate[d * NEX + myex];
    // softmax over 8 lanes (segments of 8; all segments hold identical data)
    float m = gp;
#pragma unroll
    for (int o = 1; o < 8; o <<= 1) m = fmaxf(m, __shfl_xor_sync(0xffffffffu, m, o, 8));
    float w = expf(gp - m);
    float sw = w;
#pragma unroll
    for (int o = 1; o < 8; o <<= 1) sw += __shfl_xor_sync(0xffffffffu, sw, o, 8);
    float num = de * w;
#pragma unroll
    for (int o = 1; o < 8; o <<= 1) num += __shfl_xor_sync(0xffffffffu, num, o, 8);
    if (lane == 0) {
        float ds = num / sw;
        float term = fabsf(ds / dis[e] - 1.0f);
        atomicAdd(g_loss, term);
    }
}

__global__ void k_final(float* __restrict__ lossp, float invE2) {
    lossp[0] = g_loss[0] * invE2;
}

extern "C" void kernel_launch(void* const* d_in, const int* in_sizes, int n_in,
                              void* d_out, int out_size) {
    const float* x0   = (const float*)d_in[0];
    const float* x1   = (const float*)d_in[1];
    const float* W1   = (const float*)d_in[2];
    const float* b1   = (const float*)d_in[3];
    const float* W2   = (const float*)d_in[4];
    const float* b2   = (const float*)d_in[5];
    const float* Wc   = (const float*)d_in[6];
    const float* bc   = (const float*)d_in[7];
    const float* emb  = (const float*)d_in[8];
    const float* dis  = (const float*)d_in[9];
    const int*   ei0  = (const int*)d_in[10];
    const int*   ei1  = (const int*)d_in[11];
    const int*   bat0 = (const int*)d_in[12];
    const int*   bat1 = (const int*)d_in[13];
    const int*   ei2  = (const int*)d_in[14];

    int N  = in_sizes[0] / 64;
    int E  = in_sizes[10] / 2;
    int B  = in_sizes[8] / (NEX * EMBD);
    int E2 = in_sizes[14] / 2;

    float* out = (float*)d_out;
    float* lossp = out + (out_size - 1);

    void *p_dinv, *p_agg, *p_pool, *p_cnt, *p_loss, *p_h;
    cudaGetSymbolAddress(&p_dinv, g_dinv);
    cudaGetSymbolAddress(&p_agg,  g_agg);
    cudaGetSymbolAddress(&p_pool, g_pool);
    cudaGetSymbolAddress(&p_cnt,  g_cnt);
    cudaGetSymbolAddress(&p_loss, g_loss);
    cudaGetSymbolAddress(&p_h,    g_h);

    const int T = 256;
    cudaMemsetAsync(p_pool, 0, (size_t)NB * 64 * sizeof(float));
    cudaMemsetAsync(p_cnt,  0, (size_t)2 * NB * sizeof(float));
    cudaMemsetAsync(p_loss, 0, sizeof(float));

    for (int scale = 0; scale < 2; scale++) {
        const float* x    = scale ? x1 : x0;
        const int*   ei   = scale ? ei1 : ei0;
        const int*   bat  = scale ? bat1 : bat0;
        const int* src = ei;
        const int* dst = ei + E;

        // degree -> dinv
        cudaMemsetAsync(p_dinv, 0, (size_t)N * sizeof(float));
        k_deg<<<(E + T - 1) / T, T>>>(dst, E);
        k_dinv<<<(N + T - 1) / T, T>>>(N);

        // conv1: xw = x@W1 ; agg ; h = agg + dinv^2*xw + b1
        k_gemm<64><<<(N + T - 1) / T, T>>>(x, W1, N);
        cudaMemsetAsync(p_agg, 0, (size_t)N * 64 * sizeof(float));
        k_scatter<16><<<((long)E * 16 + T - 1) / T, T>>>(src, dst, E);
        k_selfbias<16><<<((long)N * 16 + T - 1) / T, T>>>(b1, N);

        // conv2: xw2 = h@W2 ; agg ; h2 = agg + dinv^2*xw2 + b2
        k_gemm<32><<<(N + T - 1) / T, T>>>((const float*)p_h, W2, N);
        cudaMemsetAsync(p_agg, 0, (size_t)N * 32 * sizeof(float));
        k_scatter<8><<<((long)E * 8 + T - 1) / T, T>>>(src, dst, E);
        k_selfbias<8><<<((long)N * 8 + T - 1) / T, T>>>(b2, N);

        // mean-pool accumulate
        k_pool<<<((long)N * 8 + T - 1) / T, T>>>(bat, N, scale);
    }

    // gating softmax -> d_out[0 .. B*8)
    k_gate<<<(B + T - 1) / T, T>>>(Wc, bc, out, B);

    // distortion loss over graph edges (reads gate from d_out)
    k_loss<<<((long)E2 * 32 + T - 1) / T, T>>>(emb, out, dis, ei2, E2);
    k_final<<<1, 1>>>(lossp, 1.0f / (float)E2);
}

// round 2
// speedup vs baseline: 1.0861x; 1.0861x over previous
#include <cuda_runtime.h>
#include <math.h>

#define NN   50000
#define NE_  800000
#define NB   4096
#define NEX  8
#define EMBD 64
#define E2M  131072

// ---- device scratch (no allocations allowed) ----
__device__ __align__(16) float g_xw[NN * 64];   // xs = dinv * (X@W)
__device__ __align__(16) float g_h[NN * 64];    // hidden after conv1
__device__ __align__(16) float g_dinv[NN];
__device__ __align__(16) int   g_cnt_i[NN];
__device__ __align__(16) int   g_starts[NN + 1];
__device__ __align__(16) int   g_cursor[NN];
__device__ __align__(16) int   g_csr[NE_];
__device__ __align__(16) float g_pool[NB * 64];
__device__ __align__(16) float g_cnt[2 * NB];
__device__ __align__(16) int   g_bins2[NB];
__device__ __align__(16) int   g_starts2[NB + 1];
__device__ __align__(16) int   g_cursor2[NB];
__device__ __align__(16) int   g_order[E2M];
__device__ float g_loss[1];

static __device__ __forceinline__ void red_add_v4(float4* p, float4 v) {
    asm volatile("red.global.add.v4.f32 [%0], {%1, %2, %3, %4};"
                 :: "l"(p), "f"(v.x), "f"(v.y), "f"(v.z), "f"(v.w)
                 : "memory");
}

// ---------------- histogram of int keys ----------------
__global__ void k_hist(const int* __restrict__ key, int* __restrict__ bins, int n) {
    int e = blockIdx.x * blockDim.x + threadIdx.x;
    if (e < n) atomicAdd(&bins[key[e]], 1);
}

// ---------------- single-block exclusive scan (+cursor copy, optional dinv) ----------------
__global__ void k_scan(const int* __restrict__ cnt, int n,
                       int* __restrict__ starts, int* __restrict__ cursor,
                       float* __restrict__ dinv, int total) {
    __shared__ int ts[1024];
    int t = threadIdx.x;
    int CH = (n + 1023) >> 10;
    int beg = t * CH;
    int end = min(beg + CH, n);
    int s = 0;
    for (int i = beg; i < end; i++) s += cnt[i];
    ts[t] = s;
    __syncthreads();
    for (int o = 1; o < 1024; o <<= 1) {
        int u = (t >= o) ? ts[t - o] : 0;
        __syncthreads();
        ts[t] += u;
        __syncthreads();
    }
    int off = ts[t] - s;   // exclusive
    for (int i = beg; i < end; i++) {
        starts[i] = off;
        cursor[i] = off;
        if (dinv) dinv[i] = rsqrtf((float)cnt[i] + 1.0f);
        off += cnt[i];
    }
    if (t == 0) starts[n] = total;
}

// ---------------- CSR fill: csr[pos(dst)] = src ----------------
__global__ void k_fill(const int* __restrict__ src, const int* __restrict__ dst, int E) {
    int e = blockIdx.x * blockDim.x + threadIdx.x;
    if (e >= E) return;
    int pos = atomicAdd(&g_cursor[dst[e]], 1);
    g_csr[pos] = src[e];
}

// ---------------- edge-id bucket fill (loss) ----------------
__global__ void k_fill2(const int* __restrict__ srow, int E2) {
    int e = blockIdx.x * blockDim.x + threadIdx.x;
    if (e >= E2) return;
    int pos = atomicAdd(&g_cursor2[srow[e]], 1);
    g_order[pos] = e;
}

// ---------------- GEMM: g_xw = dinv * (X @ W), X [n,64], W [64,KOUT] ----------------
template <int KOUT>
__global__ void k_gemm(const float* __restrict__ X, const float* __restrict__ W, int n) {
    __shared__ float Ws[64 * KOUT];
    for (int i = threadIdx.x; i < 64 * KOUT; i += blockDim.x) Ws[i] = W[i];
    __syncthreads();
    int row = blockIdx.x * blockDim.x + threadIdx.x;
    if (row >= n) return;

    float xr[64];
    const float4* x4 = (const float4*)(X + row * 64);
#pragma unroll
    for (int j = 0; j < 16; j++) {
        float4 v = x4[j];
        xr[4 * j + 0] = v.x; xr[4 * j + 1] = v.y;
        xr[4 * j + 2] = v.z; xr[4 * j + 3] = v.w;
    }
    float acc[KOUT];
#pragma unroll
    for (int c = 0; c < KOUT; c++) acc[c] = 0.0f;
#pragma unroll 4
    for (int k = 0; k < 64; k++) {
        float xk = xr[k];
#pragma unroll
        for (int c = 0; c < KOUT; c++) acc[c] += xk * Ws[k * KOUT + c];
    }
    float di = g_dinv[row];
    float4* y4 = (float4*)(g_xw + row * KOUT);
#pragma unroll
    for (int j = 0; j < KOUT / 4; j++)
        y4[j] = make_float4(di * acc[4 * j], di * acc[4 * j + 1],
                            di * acc[4 * j + 2], di * acc[4 * j + 3]);
}

// ------------- gather conv1: h = dinv_d*(sum_in xs + xs_d) + b1  (C=64, 16 lanes/node) -------------
__global__ void k_gather1(const float* __restrict__ bias, int n) {
    int idx = blockIdx.x * blockDim.x + threadIdx.x;
    int i = idx >> 4;
    int q = idx & 15;
    if (i >= n) return;
    const float4* xs4 = (const float4*)g_xw;
    float4 acc = xs4[i * 16 + q];     // self term
    int b0 = g_starts[i], b1 = g_starts[i + 1];
    int j = b0;
    for (; j + 1 < b1; j += 2) {
        int s0 = g_csr[j], s1 = g_csr[j + 1];
        float4 v0 = xs4[s0 * 16 + q];
        float4 v1 = xs4[s1 * 16 + q];
        acc.x += v0.x + v1.x; acc.y += v0.y + v1.y;
        acc.z += v0.z + v1.z; acc.w += v0.w + v1.w;
    }
    if (j < b1) {
        float4 v = xs4[g_csr[j] * 16 + q];
        acc.x += v.x; acc.y += v.y; acc.z += v.z; acc.w += v.w;
    }
    float di = g_dinv[i];
    float4 bq = ((const float4*)bias)[q];
    ((float4*)g_h)[i * 16 + q] = make_float4(di * acc.x + bq.x, di * acc.y + bq.y,
                                             di * acc.z + bq.z, di * acc.w + bq.w);
}

// ------------- gather conv2 + fused mean-pool accumulate (C=32, 8 lanes/node) -------------
__global__ void k_gather2(const float* __restrict__ bias, const int* __restrict__ batch,
                          int n, int scale) {
    int idx = blockIdx.x * blockDim.x + threadIdx.x;
    int i = idx >> 3;
    int q = idx & 7;
    if (i >= n) return;
    const float4* xs4 = (const float4*)g_xw;
    float4 acc = xs4[i * 8 + q];
    int b0 = g_starts[i], b1 = g_starts[i + 1];
    int j = b0;
    for (; j + 1 < b1; j += 2) {
        int s0 = g_csr[j], s1 = g_csr[j + 1];
        float4 v0 = xs4[s0 * 8 + q];
        float4 v1 = xs4[s1 * 8 + q];
        acc.x += v0.x + v1.x; acc.y += v0.y + v1.y;
        acc.z += v0.z + v1.z; acc.w += v0.w + v1.w;
    }
    if (j < b1) {
        float4 v = xs4[g_csr[j] * 8 + q];
        acc.x += v.x; acc.y += v.y; acc.z += v.z; acc.w += v.w;
    }
    float di = g_dinv[i];
    float4 bq = ((const float4*)bias)[q];
    float4 h2 = make_float4(di * acc.x + bq.x, di * acc.y + bq.y,
                            di * acc.z + bq.z, di * acc.w + bq.w);
    int b = batch[i];
    red_add_v4(((float4*)g_pool) + b * 16 + scale * 8 + q, h2);
}

// ---------------- per-graph node count ----------------
__global__ void k_cnt(const int* __restrict__ batch, int n, int scale) {
    int i = blockIdx.x * blockDim.x + threadIdx.x;
    if (i < n) atomicAdd(&g_cnt[scale * NB + batch[i]], 1.0f);
}

// ---------------- gate = softmax(concat(x0,x1) @ Wc + bc) ----------------
__global__ void k_gate(const float* __restrict__ Wc, const float* __restrict__ bc,
                       float* __restrict__ out, int B) {
    int b = blockIdx.x * blockDim.x + threadIdx.x;
    if (b >= B) return;
    float inv0 = 1.0f / fmaxf(g_cnt[b], 1.0f);
    float inv1 = 1.0f / fmaxf(g_cnt[NB + b], 1.0f);
    float logit[NEX];
#pragma unroll
    for (int e = 0; e < NEX; e++) logit[e] = bc[e];
    const float* pr = g_pool + b * 64;
    for (int k = 0; k < 64; k++) {
        float xv = pr[k] * (k < 32 ? inv0 : inv1);
#pragma unroll
        for (int e = 0; e < NEX; e++) logit[e] += xv * Wc[k * NEX + e];
    }
    float m = logit[0];
#pragma unroll
    for (int e = 1; e < NEX; e++) m = fmaxf(m, logit[e]);
    float ssum = 0.0f;
#pragma unroll
    for (int e = 0; e < NEX; e++) { logit[e] = expf(logit[e] - m); ssum += logit[e]; }
    float is = 1.0f / ssum;
#pragma unroll
    for (int e = 0; e < NEX; e++) out[b * NEX + e] = logit[e] * is;
}

// ---------- distortion loss, bucketed by source graph: 1 block per graph ----------
__global__ void k_loss(const float* __restrict__ emb, const float* __restrict__ gate,
                       const float* __restrict__ dis, const int* __restrict__ ei2, int E2) {
    __shared__ float sa[NEX * EMBD];       // emb[g] row (512 floats)
    __shared__ float warp_part[8];
    int g = blockIdx.x;
    int tid = threadIdx.x;
    for (int i = tid; i < NEX * EMBD; i += blockDim.x)
        sa[i] = emb[(long)g * (NEX * EMBD) + i];
    __syncthreads();

    int lane = tid & 31;
    int w = tid >> 5;
    int myex = lane & 7;
    int ex = lane >> 2;
    int ch = lane & 3;
    float gs = gate[g * NEX + myex];
    const float4* Ap = ((const float4*)sa) + ex * 16 + ch * 4;

    float part = 0.0f;
    int b0 = g_starts2[g], b1 = g_starts2[g + 1];
    for (int j = b0 + w; j < b1; j += 8) {
        int e = g_order[j];
        int d = ei2[E2 + e];
        const float4* Bp = (const float4*)(emb + (long)d * (NEX * EMBD)) + ex * 16 + ch * 4;
        float acc = 0.0f;
#pragma unroll
        for (int k = 0; k < 4; k++) {
            float4 a = Ap[k], b = Bp[k];
            float dx = a.x - b.x, dy = a.y - b.y, dz = a.z - b.z, dw = a.w - b.w;
            acc += dx * dx + dy * dy + dz * dz + dw * dw;
        }
        acc += __shfl_xor_sync(0xffffffffu, acc, 1);
        acc += __shfl_xor_sync(0xffffffffu, acc, 2);
        float de = __shfl_sync(0xffffffffu, acc, (lane & 7) * 4);
        float gp = gs * gate[d * NEX + myex];
        float m = gp;
#pragma unroll
        for (int o = 1; o < 8; o <<= 1) m = fmaxf(m, __shfl_xor_sync(0xffffffffu, m, o, 8));
        float wgt = expf(gp - m);
        float sw = wgt;
#pragma unroll
        for (int o = 1; o < 8; o <<= 1) sw += __shfl_xor_sync(0xffffffffu, sw, o, 8);
        float num = de * wgt;
#pragma unroll
        for (int o = 1; o < 8; o <<= 1) num += __shfl_xor_sync(0xffffffffu, num, o, 8);
        if (lane == 0) part += fabsf(num / sw / dis[e] - 1.0f);
    }
    if (lane == 0) warp_part[w] = part;
    __syncthreads();
    if (tid == 0) {
        float s = 0.0f;
#pragma unroll
        for (int k = 0; k < 8; k++) s += warp_part[k];
        atomicAdd(g_loss, s);
    }
}

__global__ void k_final(float* __restrict__ lossp, float invE2) {
    lossp[0] = g_loss[0] * invE2;
}

extern "C" void kernel_launch(void* const* d_in, const int* in_sizes, int n_in,
                              void* d_out, int out_size) {
    const float* x0   = (const float*)d_in[0];
    const float* x1   = (const float*)d_in[1];
    const float* W1   = (const float*)d_in[2];
    const float* b1   = (const float*)d_in[3];
    const float* W2   = (const float*)d_in[4];
    const float* b2   = (const float*)d_in[5];
    const float* Wc   = (const float*)d_in[6];
    const float* bc   = (const float*)d_in[7];
    const float* emb  = (const float*)d_in[8];
    const float* dis  = (const float*)d_in[9];
    const int*   ei0  = (const int*)d_in[10];
    const int*   ei1  = (const int*)d_in[11];
    const int*   bat0 = (const int*)d_in[12];
    const int*   bat1 = (const int*)d_in[13];
    const int*   ei2  = (const int*)d_in[14];

    int N  = in_sizes[0] / 64;
    int E  = in_sizes[10] / 2;
    int B  = in_sizes[8] / (NEX * EMBD);
    int E2 = in_sizes[14] / 2;

    float* out = (float*)d_out;
    float* lossp = out + (out_size - 1);

    void *p_cnt_i, *p_starts, *p_cursor, *p_dinv, *p_pool, *p_cnt, *p_loss, *p_h;
    void *p_bins2, *p_starts2, *p_cursor2;
    cudaGetSymbolAddress(&p_cnt_i,  g_cnt_i);
    cudaGetSymbolAddress(&p_starts, g_starts);
    cudaGetSymbolAddress(&p_cursor, g_cursor);
    cudaGetSymbolAddress(&p_dinv,   g_dinv);
    cudaGetSymbolAddress(&p_pool,   g_pool);
    cudaGetSymbolAddress(&p_cnt,    g_cnt);
    cudaGetSymbolAddress(&p_loss,   g_loss);
    cudaGetSymbolAddress(&p_h,      g_h);
    cudaGetSymbolAddress(&p_bins2,  g_bins2);
    cudaGetSymbolAddress(&p_starts2, g_starts2);
    cudaGetSymbolAddress(&p_cursor2, g_cursor2);

    const int T = 256;
    cudaMemsetAsync(p_pool, 0, (size_t)NB * 64 * sizeof(float));
    cudaMemsetAsync(p_cnt,  0, (size_t)2 * NB * sizeof(float));
    cudaMemsetAsync(p_loss, 0, sizeof(float));

    for (int scale = 0; scale < 2; scale++) {
        const float* x   = scale ? x1 : x0;
        const int*   ei  = scale ? ei1 : ei0;
        const int*   bat = scale ? bat1 : bat0;
        const int* src = ei;
        const int* dst = ei + E;

        // CSR build on dst (+ dinv from degree)
        cudaMemsetAsync(p_cnt_i, 0, (size_t)N * sizeof(int));
        k_hist<<<(E + T - 1) / T, T>>>(dst, (int*)p_cnt_i, E);
        k_scan<<<1, 1024>>>((const int*)p_cnt_i, N, (int*)p_starts, (int*)p_cursor,
                            (float*)p_dinv, E);
        k_fill<<<(E + T - 1) / T, T>>>(src, dst, E);

        // conv1
        k_gemm<64><<<(N + T - 1) / T, T>>>(x, W1, N);
        k_gather1<<<((long)N * 16 + T - 1) / T, T>>>(b1, N);
        // conv2 + pool
        k_gemm<32><<<(N + T - 1) / T, T>>>((const float*)p_h, W2, N);
        k_gather2<<<((long)N * 8 + T - 1) / T, T>>>(b2, bat, N, scale);
        k_cnt<<<(N + T - 1) / T, T>>>(bat, N, scale);
    }

    // gating softmax -> d_out[0 .. B*8)
    k_gate<<<(B + T - 1) / T, T>>>(Wc, bc, out, B);

    // bucket loss edges by source graph
    cudaMemsetAsync(p_bins2, 0, (size_t)NB * sizeof(int));
    k_hist<<<(E2 + T - 1) / T, T>>>(ei2, (int*)p_bins2, E2);
    k_scan<<<1, 1024>>>((const int*)p_bins2, B, (int*)p_starts2, (int*)p_cursor2,
                        (float*)0, E2);
    k_fill2<<<(E2 + T - 1) / T, T>>>(ei2, E2);

    // distortion loss (block per source graph) + finalize
    k_loss<<<B, 256>>>(emb, out, dis, ei2, E2);
    k_final<<<1, 1>>>(lossp, 1.0f / (float)E2);
}